// round 11
// baseline (speedup 1.0000x reference)
#include <cuda_runtime.h>
#include <math.h>

#define IMG_H 200
#define IMG_W 200
#define IMG_C 256
#define PIX_BYTES (IMG_C * 4)   // 1024 bytes per pixel
#define MAX_PP 64               // supports ps up to 8

struct CellGeom {
    unsigned o00, o01, o10, o11;  // BYTE offsets of the 4 corner pixels
    float w00, w01, w10, w11;     // folded bilinear product weights
};

// One CTA (256 thr = 8 warps) per RoI. Geometry (offsets + product weights,
// with exact clamp-folding) into smem; cells classified into full-bilinear
// and partial lists. Full cells processed in PAIRS per warp iteration
// (8 loads -> 2 blends -> 8 loads -> 2 blends): doubles the issue burst per
// memory stall at unchanged in-flight load count. Partial cells use the
// reduced-load paths (1 or 2 corners).
__global__ __launch_bounds__(256, 4) void roipool_kernel(
        const float* __restrict__ img,
        const float* __restrict__ rois,
        float* __restrict__ out,
        int ps) {
    __shared__ CellGeom geom[MAX_PP];
    __shared__ unsigned char order[MAX_PP];  // fulls first, partials at end
    __shared__ int s_nfull;

    const int r    = blockIdx.x;
    const int warp = threadIdx.x >> 5;
    const int lane = threadIdx.x & 31;
    const int pp   = ps * ps;

    const float4 rv = reinterpret_cast<const float4*>(rois)[r];
    const int x = (int)rv.x;
    const int y = (int)rv.y;
    const int w = (int)rv.z;
    const int h = (int)rv.w;

    if (threadIdx.x < pp) {
        const int cell = threadIdx.x;
        const int py = cell / ps;
        const int px = cell - py * ps;

        const float sy = (float)h / (float)ps;
        const float sx = (float)w / (float)ps;
        const float src_y = (float)py * sy;
        const float src_x = (float)px * sx;
        const int y0 = (int)floorf(src_y);
        const int x0 = (int)floorf(src_x);

        const int gy0 = min(max(y + min(max(y0,     0), h - 1), 0), IMG_H - 1);
        const int gy1 = min(max(y + min(max(y0 + 1, 0), h - 1), 0), IMG_H - 1);
        const int gx0 = min(max(x + min(max(x0,     0), w - 1), 0), IMG_W - 1);
        const int gx1 = min(max(x + min(max(x0 + 1, 0), w - 1), 0), IMG_W - 1);

        float wx = src_x - (float)x0;
        float wy = src_y - (float)y0;
        // Exact fold: duplicated (clamped) corners contribute identically,
        // so zero the fractional weight and let the kept corner absorb it.
        if (gx0 == gx1) wx = 0.0f;
        if (gy0 == gy1) wy = 0.0f;

        CellGeom g;
        g.o00 = (unsigned)(gy0 * IMG_W + gx0) * PIX_BYTES;
        g.o01 = (unsigned)(gy0 * IMG_W + gx1) * PIX_BYTES;
        g.o10 = (unsigned)(gy1 * IMG_W + gx0) * PIX_BYTES;
        g.o11 = (unsigned)(gy1 * IMG_W + gx1) * PIX_BYTES;
        g.w00 = (1.0f - wx) * (1.0f - wy);
        g.w01 = wx * (1.0f - wy);
        g.w10 = (1.0f - wx) * wy;
        g.w11 = wx * wy;
        geom[cell] = g;
    }
    __syncthreads();

    if (threadIdx.x == 0) {
        int nf = 0, np = 0;
        for (int c = 0; c < pp; c++) {
            if (geom[c].w11 != 0.0f) order[nf++] = (unsigned char)c;   // full
            else                     order[pp - 1 - (np++)] = (unsigned char)c;
        }
        s_nfull = nf;
    }
    __syncthreads();

    const unsigned ca = (unsigned)lane * 16u;
    const char* __restrict__ ib = reinterpret_cast<const char*>(img) + ca;
    char* __restrict__ ob = reinterpret_cast<char*>(out)
                          + (unsigned)r * (unsigned)pp * PIX_BYTES + ca;

#define LD4(off) (*reinterpret_cast<const float4*>(ib + (off)))
#define BLEND4(d, g, p00, p01, p10, p11)                                     \
    do {                                                                     \
        (d).x = (g).w00*(p00).x + (g).w01*(p01).x + (g).w10*(p10).x + (g).w11*(p11).x; \
        (d).y = (g).w00*(p00).y + (g).w01*(p01).y + (g).w10*(p10).y + (g).w11*(p11).y; \
        (d).z = (g).w00*(p00).z + (g).w01*(p01).z + (g).w10*(p10).z + (g).w11*(p11).z; \
        (d).w = (g).w00*(p00).w + (g).w01*(p01).w + (g).w10*(p10).w + (g).w11*(p11).w; \
    } while (0)

    const int nfull  = s_nfull;
    const int npairs = nfull >> 1;

    // ---- full-bilinear cells, two per warp iteration ----
    for (int p = warp; p < npairs; p += 8) {
        const int c1 = order[2 * p];
        const int c2 = order[2 * p + 1];
        const CellGeom g1 = geom[c1];
        const CellGeom g2 = geom[c2];
        char* o1 = ob + (unsigned)c1 * PIX_BYTES;
        char* o2 = ob + (unsigned)c2 * PIX_BYTES;

        // phase A: channel-half A of both cells (8 loads in flight)
        {
            const float4 u00 = LD4(g1.o00);
            const float4 u01 = LD4(g1.o01);
            const float4 u10 = LD4(g1.o10);
            const float4 u11 = LD4(g1.o11);
            const float4 v00 = LD4(g2.o00);
            const float4 v01 = LD4(g2.o01);
            const float4 v10 = LD4(g2.o10);
            const float4 v11 = LD4(g2.o11);
            float4 r1, r2;
            BLEND4(r1, g1, u00, u01, u10, u11);
            BLEND4(r2, g2, v00, v01, v10, v11);
            *reinterpret_cast<float4*>(o1) = r1;
            *reinterpret_cast<float4*>(o2) = r2;
        }
        // phase B: channel-half B of both cells
        {
            const float4 u00 = LD4(g1.o00 + 512u);
            const float4 u01 = LD4(g1.o01 + 512u);
            const float4 u10 = LD4(g1.o10 + 512u);
            const float4 u11 = LD4(g1.o11 + 512u);
            const float4 v00 = LD4(g2.o00 + 512u);
            const float4 v01 = LD4(g2.o01 + 512u);
            const float4 v10 = LD4(g2.o10 + 512u);
            const float4 v11 = LD4(g2.o11 + 512u);
            float4 r1, r2;
            BLEND4(r1, g1, u00, u01, u10, u11);
            BLEND4(r2, g2, v00, v01, v10, v11);
            *reinterpret_cast<float4*>(o1 + 512u) = r1;
            *reinterpret_cast<float4*>(o2 + 512u) = r2;
        }
    }

    // ---- singles: leftover full (if odd) + partial cells ----
    for (int s = npairs * 2 + warp; s < pp; s += 8) {
        const int cell = order[s];
        const CellGeom g = geom[cell];
        char* oc = ob + (unsigned)cell * PIX_BYTES;
        float4* __restrict__ oa  = reinterpret_cast<float4*>(oc);
        float4* __restrict__ obp = reinterpret_cast<float4*>(oc + 512u);

        const bool zx = (g.w01 == 0.0f) && (g.w11 == 0.0f);
        const bool zy = (g.w10 == 0.0f) && (g.w11 == 0.0f);

        if (zx && zy) {
            *oa  = LD4(g.o00);
            *obp = LD4(g.o00 + 512u);
        } else if (zx) {
            const float4 a0 = LD4(g.o00);
            const float4 a1 = LD4(g.o10);
            const float4 b0 = LD4(g.o00 + 512u);
            const float4 b1 = LD4(g.o10 + 512u);
            float4 ra, rb;
            ra.x = g.w00*a0.x + g.w10*a1.x;  ra.y = g.w00*a0.y + g.w10*a1.y;
            ra.z = g.w00*a0.z + g.w10*a1.z;  ra.w = g.w00*a0.w + g.w10*a1.w;
            rb.x = g.w00*b0.x + g.w10*b1.x;  rb.y = g.w00*b0.y + g.w10*b1.y;
            rb.z = g.w00*b0.z + g.w10*b1.z;  rb.w = g.w00*b0.w + g.w10*b1.w;
            *oa = ra; *obp = rb;
        } else if (zy) {
            const float4 a0 = LD4(g.o00);
            const float4 a1 = LD4(g.o01);
            const float4 b0 = LD4(g.o00 + 512u);
            const float4 b1 = LD4(g.o01 + 512u);
            float4 ra, rb;
            ra.x = g.w00*a0.x + g.w01*a1.x;  ra.y = g.w00*a0.y + g.w01*a1.y;
            ra.z = g.w00*a0.z + g.w01*a1.z;  ra.w = g.w00*a0.w + g.w01*a1.w;
            rb.x = g.w00*b0.x + g.w01*b1.x;  rb.y = g.w00*b0.y + g.w01*b1.y;
            rb.z = g.w00*b0.z + g.w01*b1.z;  rb.w = g.w00*b0.w + g.w01*b1.w;
            *oa = ra; *obp = rb;
        } else {
            const float4 a00 = LD4(g.o00);
            const float4 a01 = LD4(g.o01);
            const float4 a10 = LD4(g.o10);
            const float4 a11 = LD4(g.o11);
            const float4 b00 = LD4(g.o00 + 512u);
            const float4 b01 = LD4(g.o01 + 512u);
            const float4 b10 = LD4(g.o10 + 512u);
            const float4 b11 = LD4(g.o11 + 512u);
            float4 ra, rb;
            BLEND4(ra, g, a00, a01, a10, a11);
            BLEND4(rb, g, b00, b01, b10, b11);
            *oa = ra; *obp = rb;
        }
    }
#undef BLEND4
#undef LD4
}

extern "C" void kernel_launch(void* const* d_in, const int* in_sizes, int n_in,
                              void* d_out, int out_size) {
    const float* img  = (const float*)d_in[0];
    const float* rois = (const float*)d_in[1];
    float* out = (float*)d_out;

    const int n_rois = in_sizes[1] / 4;
    const int pp = out_size / (n_rois * IMG_C);
    int ps = (int)(sqrtf((float)pp) + 0.5f);
    if (ps < 1) ps = 1;
    if (ps * ps > MAX_PP) ps = 8;

    roipool_kernel<<<n_rois, 256>>>(img, rois, out, ps);
}

// round 12
// speedup vs baseline: 1.2557x; 1.2557x over previous
#include <cuda_runtime.h>
#include <math.h>

#define IMG_H 200
#define IMG_W 200
#define IMG_C 256
#define PIX_BYTES (IMG_C * 4)   // 1024 bytes per pixel
#define MAX_PP 64               // supports ps up to 8

struct CellGeom {
    unsigned o00, o01, o10, o11;  // BYTE offsets of the 4 corner pixels
    float wx, wy;
};

// R7 champion structure, single change: evict-first (__stcs) output stores.
// One CTA (256 thr = 8 warps) per RoI. Geometry once into smem. Each warp does
// one full cell per iteration (8 independent LDG.128 -> MLP 8). Cells with
// wx==0 / wy==0 skip the unused corner loads (warp-uniform branches).
__global__ __launch_bounds__(256, 5) void roipool_kernel(
        const float* __restrict__ img,
        const float* __restrict__ rois,
        float* __restrict__ out,
        int ps) {
    __shared__ CellGeom geom[MAX_PP];

    const int r    = blockIdx.x;
    const int warp = threadIdx.x >> 5;
    const int lane = threadIdx.x & 31;
    const int pp   = ps * ps;

    const float4 rv = reinterpret_cast<const float4*>(rois)[r];
    const int x = (int)rv.x;
    const int y = (int)rv.y;
    const int w = (int)rv.z;
    const int h = (int)rv.w;

    if (threadIdx.x < pp) {
        const int cell = threadIdx.x;
        const int py = cell / ps;
        const int px = cell - py * ps;

        const float sy = (float)h / (float)ps;
        const float sx = (float)w / (float)ps;
        const float src_y = (float)py * sy;
        const float src_x = (float)px * sx;
        const int y0 = (int)floorf(src_y);
        const int x0 = (int)floorf(src_x);

        const int gy0 = min(max(y + min(max(y0,     0), h - 1), 0), IMG_H - 1);
        const int gy1 = min(max(y + min(max(y0 + 1, 0), h - 1), 0), IMG_H - 1);
        const int gx0 = min(max(x + min(max(x0,     0), w - 1), 0), IMG_W - 1);
        const int gx1 = min(max(x + min(max(x0 + 1, 0), w - 1), 0), IMG_W - 1);

        CellGeom g;
        g.o00 = (unsigned)(gy0 * IMG_W + gx0) * PIX_BYTES;
        g.o01 = (unsigned)(gy0 * IMG_W + gx1) * PIX_BYTES;
        g.o10 = (unsigned)(gy1 * IMG_W + gx0) * PIX_BYTES;
        g.o11 = (unsigned)(gy1 * IMG_W + gx1) * PIX_BYTES;
        g.wx  = src_x - (float)x0;
        g.wy  = src_y - (float)y0;
        geom[cell] = g;
    }
    __syncthreads();

    const char* __restrict__ ib = reinterpret_cast<const char*>(img);
    char* __restrict__ ob = reinterpret_cast<char*>(out)
                          + (unsigned)r * (unsigned)pp * PIX_BYTES;

    const unsigned ca = (unsigned)lane * 16u;   // byte offset of channel-half A
    const unsigned cb = ca + 512u;              // channel-half B

#define LD4(off) (*reinterpret_cast<const float4*>(ib + (off)))

    for (int cell = warp; cell < pp; cell += 8) {
        const CellGeom g = geom[cell];          // broadcast LDS
        char* oc = ob + (unsigned)cell * PIX_BYTES;
        float4* __restrict__ oa  = reinterpret_cast<float4*>(oc + ca);
        float4* __restrict__ obp = reinterpret_cast<float4*>(oc + cb);

        const float wx = g.wx, wy = g.wy;
        const bool zx = (wx == 0.0f);
        const bool zy = (wy == 0.0f);

        if (zx && zy) {
            __stcs(oa,  LD4(g.o00 + ca));
            __stcs(obp, LD4(g.o00 + cb));
        } else if (zx) {
            const float4 a00 = LD4(g.o00 + ca);
            const float4 a10 = LD4(g.o10 + ca);
            const float4 b00 = LD4(g.o00 + cb);
            const float4 b10 = LD4(g.o10 + cb);
            const float omwy = 1.0f - wy;
            float4 ra, rb;
            ra.x = a00.x * omwy + a10.x * wy;
            ra.y = a00.y * omwy + a10.y * wy;
            ra.z = a00.z * omwy + a10.z * wy;
            ra.w = a00.w * omwy + a10.w * wy;
            rb.x = b00.x * omwy + b10.x * wy;
            rb.y = b00.y * omwy + b10.y * wy;
            rb.z = b00.z * omwy + b10.z * wy;
            rb.w = b00.w * omwy + b10.w * wy;
            __stcs(oa,  ra);
            __stcs(obp, rb);
        } else if (zy) {
            const float4 a00 = LD4(g.o00 + ca);
            const float4 a01 = LD4(g.o01 + ca);
            const float4 b00 = LD4(g.o00 + cb);
            const float4 b01 = LD4(g.o01 + cb);
            const float omwx = 1.0f - wx;
            float4 ra, rb;
            ra.x = a00.x * omwx + a01.x * wx;
            ra.y = a00.y * omwx + a01.y * wx;
            ra.z = a00.z * omwx + a01.z * wx;
            ra.w = a00.w * omwx + a01.w * wx;
            rb.x = b00.x * omwx + b01.x * wx;
            rb.y = b00.y * omwx + b01.y * wx;
            rb.z = b00.z * omwx + b01.z * wx;
            rb.w = b00.w * omwx + b01.w * wx;
            __stcs(oa,  ra);
            __stcs(obp, rb);
        } else {
            const float4 a00 = LD4(g.o00 + ca);
            const float4 a01 = LD4(g.o01 + ca);
            const float4 a10 = LD4(g.o10 + ca);
            const float4 a11 = LD4(g.o11 + ca);
            const float4 b00 = LD4(g.o00 + cb);
            const float4 b01 = LD4(g.o01 + cb);
            const float4 b10 = LD4(g.o10 + cb);
            const float4 b11 = LD4(g.o11 + cb);

            const float omwx = 1.0f - wx;
            const float omwy = 1.0f - wy;
            float4 ra, rb;
            {
                float t, b;
                t = a00.x * omwx + a01.x * wx; b = a10.x * omwx + a11.x * wx; ra.x = t * omwy + b * wy;
                t = a00.y * omwx + a01.y * wx; b = a10.y * omwx + a11.y * wx; ra.y = t * omwy + b * wy;
                t = a00.z * omwx + a01.z * wx; b = a10.z * omwx + a11.z * wx; ra.z = t * omwy + b * wy;
                t = a00.w * omwx + a01.w * wx; b = a10.w * omwx + a11.w * wx; ra.w = t * omwy + b * wy;

                t = b00.x * omwx + b01.x * wx; b = b10.x * omwx + b11.x * wx; rb.x = t * omwy + b * wy;
                t = b00.y * omwx + b01.y * wx; b = b10.y * omwx + b11.y * wx; rb.y = t * omwy + b * wy;
                t = b00.z * omwx + b01.z * wx; b = b10.z * omwx + b11.z * wx; rb.z = t * omwy + b * wy;
                t = b00.w * omwx + b01.w * wx; b = b10.w * omwx + b11.w * wx; rb.w = t * omwy + b * wy;
            }
            __stcs(oa,  ra);
            __stcs(obp, rb);
        }
    }
#undef LD4
}

extern "C" void kernel_launch(void* const* d_in, const int* in_sizes, int n_in,
                              void* d_out, int out_size) {
    const float* img  = (const float*)d_in[0];
    const float* rois = (const float*)d_in[1];
    float* out = (float*)d_out;

    const int n_rois = in_sizes[1] / 4;
    const int pp = out_size / (n_rois * IMG_C);
    int ps = (int)(sqrtf((float)pp) + 0.5f);
    if (ps < 1) ps = 1;
    if (ps * ps > MAX_PP) ps = 8;

    roipool_kernel<<<n_rois, 256>>>(img, rois, out, ps);
}